// round 1
// baseline (speedup 1.0000x reference)
#include <cuda_runtime.h>
#include <math.h>

#define BB 4
#define CIN 64
#define COUT 64
#define HH 128
#define WW 128
#define KK 9
#define HW (HH*WW)

// ------------- device scratch (static, no allocation) -------------
__device__ float g_off[BB*10*HW];        // conv1 output, channels 0..9
__device__ float g_stats1[BB*5*2];       // GN1 sum/sumsq for groups 0..4
__device__ float g_xT[BB*HW*CIN];        // x transposed to [b][h][w][ci]
__device__ float g_wT[KK*CIN*COUT];      // w_dsc transposed to [k][ci][co]
__device__ float g_outraw[BB*COUT*HW];   // conv2 output before GN2
__device__ float g_stats2[BB*16*2];      // GN2 sum/sumsq

// ------------- prep: zero stats, transpose w_dsc -------------
__global__ void prep_kernel(const float* __restrict__ w_dsc) {
    int idx = blockIdx.x*256 + threadIdx.x;
    if (idx < KK*CIN*COUT) {
        int k  = idx / (CIN*COUT);
        int r  = idx % (CIN*COUT);
        int ci = r / COUT;
        int co = r % COUT;
        g_wT[idx] = w_dsc[(co*CIN + ci)*KK + k];
    }
    if (idx < BB*5*2)  g_stats1[idx] = 0.f;
    if (idx < BB*16*2) g_stats2[idx] = 0.f;
}

// ------------- conv1: 3x3 SAME, channels 0..9 only, + GN1 partial stats ----
// block (32,4) = 128 threads; each thread computes 4 w-pixels x 10 channels.
// grid (1, 32, 4)
__global__ __launch_bounds__(128) void conv1_kernel(
        const float* __restrict__ x,
        const float* __restrict__ w_off,
        const float* __restrict__ b_off) {
    __shared__ float sw[10*576];     // [c][ci][9]
    __shared__ float s_sum[5], s_sq[5];
    int tid = threadIdx.y*32 + threadIdx.x;
    for (int i = tid; i < 5760; i += 128) sw[i] = w_off[i];
    if (tid < 5) { s_sum[tid] = 0.f; s_sq[tid] = 0.f; }
    __syncthreads();

    int b  = blockIdx.z;
    int h  = blockIdx.y*4 + threadIdx.y;
    int w0 = threadIdx.x*4;

    float acc[10][4];
    #pragma unroll
    for (int c = 0; c < 10; c++) {
        float bv = b_off[c];
        #pragma unroll
        for (int j = 0; j < 4; j++) acc[c][j] = bv;
    }

    const float* xb = x + (size_t)b*CIN*HW;
    for (int ci = 0; ci < CIN; ci++) {
        const float* xc = xb + ci*HW;
        #pragma unroll
        for (int dy = -1; dy <= 1; dy++) {
            int hy = h + dy;
            bool rv = (hy >= 0) && (hy < HH);
            float xv[6];
            #pragma unroll
            for (int j = 0; j < 6; j++) {
                int wx = w0 - 1 + j;
                xv[j] = (rv && wx >= 0 && wx < WW) ? xc[hy*WW + wx] : 0.f;
            }
            #pragma unroll
            for (int c = 0; c < 10; c++) {
                float wa = sw[c*576 + ci*9 + (dy+1)*3 + 0];
                float wb = sw[c*576 + ci*9 + (dy+1)*3 + 1];
                float wc = sw[c*576 + ci*9 + (dy+1)*3 + 2];
                #pragma unroll
                for (int j = 0; j < 4; j++)
                    acc[c][j] += wa*xv[j] + wb*xv[j+1] + wc*xv[j+2];
            }
        }
    }

    float ps[5] = {0,0,0,0,0}, pq[5] = {0,0,0,0,0};
    #pragma unroll
    for (int c = 0; c < 10; c++) {
        float4 v4;
        float* vp = (float*)&v4;
        #pragma unroll
        for (int j = 0; j < 4; j++) {
            float v = acc[c][j];
            vp[j] = v;
            ps[c>>1] += v;
            pq[c>>1] += v*v;
        }
        *(float4*)&g_off[((b*10+c)*HH + h)*WW + w0] = v4;
    }
    #pragma unroll
    for (int g = 0; g < 5; g++) {
        atomicAdd(&s_sum[g], ps[g]);
        atomicAdd(&s_sq[g],  pq[g]);
    }
    __syncthreads();
    if (tid < 5) {
        atomicAdd(&g_stats1[(b*5+tid)*2+0], s_sum[tid]);
        atomicAdd(&g_stats1[(b*5+tid)*2+1], s_sq[tid]);
    }
}

// ------------- transpose x: [b][ci][s] -> [b][s][ci] -------------
// block (32,8); grid (512, 2, 4)
__global__ __launch_bounds__(256) void transpose_kernel(const float* __restrict__ x) {
    __shared__ float tile[32][33];
    int b  = blockIdx.z;
    int s0 = blockIdx.x*32;
    int c0 = blockIdx.y*32;
    #pragma unroll
    for (int r = 0; r < 4; r++) {
        int ci = c0 + threadIdx.y + r*8;
        tile[threadIdx.y + r*8][threadIdx.x] =
            x[((size_t)b*CIN + ci)*HW + s0 + threadIdx.x];
    }
    __syncthreads();
    #pragma unroll
    for (int r = 0; r < 4; r++) {
        int s = s0 + threadIdx.y + r*8;
        g_xT[((size_t)b*HW + s)*CIN + c0 + threadIdx.x] = tile[threadIdx.x][threadIdx.y + r*8];
    }
}

// ------------- fused: GN1+tanh+cumsum -> coords -> sample -> GEMM -> stats2 ----
// grid (2, 128, 4): (w-block of 64 pixels, h, b); 256 threads.
__global__ __launch_bounds__(256) void fused_kernel(
        const float* __restrict__ g_gn_off,
        const float* __restrict__ b_gn_off,
        const float* __restrict__ b_dsc) {
    __shared__ int   s_y0[576];
    __shared__ int   s_x0[576];
    __shared__ float s_wy[576];
    __shared__ float s_v[4096];    // [p][ci] : p*64 + ci
    __shared__ float s_wk[4096];   // [ci][co]: ci*64 + co
    __shared__ float s_red[512];

    int t  = threadIdx.x;
    int b  = blockIdx.z;
    int h  = blockIdx.y;
    int w0 = blockIdx.x*64;

    // --- setup: per-pixel offsets (threads 0..63) ---
    if (t < 64) {
        int w = w0 + t;
        float tv[9];
        #pragma unroll
        for (int c = 0; c < 9; c++) {
            int g = c >> 1;
            float s = g_stats1[(b*5 + g)*2 + 0];
            float q = g_stats1[(b*5 + g)*2 + 1];
            float mean = s * (1.f/32768.f);
            float var  = q * (1.f/32768.f) - mean*mean;
            float inv  = rsqrtf(var + 1e-5f);
            float v = g_off[((b*10 + c)*HH + h)*WW + w];
            tv[c] = tanhf((v - mean)*inv*g_gn_off[c] + b_gn_off[c]);
        }
        float yoff[9];
        yoff[4] = 0.f;
        yoff[3] = tv[3];
        yoff[2] = yoff[3] + tv[2];
        yoff[1] = yoff[2] + tv[1];
        yoff[0] = yoff[1] + tv[0];
        yoff[5] = tv[5];
        yoff[6] = yoff[5] + tv[6];
        yoff[7] = yoff[6] + tv[7];
        yoff[8] = yoff[7] + tv[8];
        #pragma unroll
        for (int k = 0; k < 9; k++) {
            float yc = (float)h + yoff[k];
            yc = fminf(fmaxf(yc, 0.f), 127.f);
            int y0 = (int)floorf(yc);
            y0 = min(max(y0, 0), 127);
            float wy = yc - (float)y0;
            int x0 = w + k - 4;
            x0 = min(max(x0, 0), 127);
            s_y0[k*64 + t] = y0;
            s_x0[k*64 + t] = x0;
            s_wy[k*64 + t] = wy;
        }
    }

    int co0  = (t & 15) * 4;   // GEMM: 4 output channels
    int p0   = (t >> 4) * 4;   // GEMM: 4 pixels
    int ci0b = (t & 15) * 4;   // build: 4 input channels (vectorized)
    int pb   = t >> 4;         // build: pixel

    float acc[4][4];
    #pragma unroll
    for (int i = 0; i < 4; i++)
        #pragma unroll
        for (int j = 0; j < 4; j++) acc[i][j] = 0.f;

    const float* xTb = g_xT + (size_t)b*HW*CIN;

    for (int k = 0; k < 9; k++) {
        __syncthreads();
        // load this k-slice of weights [ci][co] (coalesced)
        #pragma unroll
        for (int i = 0; i < 16; i++)
            s_wk[t + 256*i] = g_wT[k*4096 + t + 256*i];
        // build sampled tile v[p][ci]: xw==0 so only 2-point vertical lerp
        #pragma unroll
        for (int pass = 0; pass < 4; pass++) {
            int p  = pb + 16*pass;
            int y0 = s_y0[k*64 + p];
            int x0 = s_x0[k*64 + p];
            float wy = s_wy[k*64 + p];
            int y1 = min(y0 + 1, 127);
            const float4 A = *(const float4*)(xTb + (y0*WW + x0)*CIN + ci0b);
            const float4 C = *(const float4*)(xTb + (y1*WW + x0)*CIN + ci0b);
            float4 v;
            v.x = A.x + wy*(C.x - A.x);
            v.y = A.y + wy*(C.y - A.y);
            v.z = A.z + wy*(C.z - A.z);
            v.w = A.w + wy*(C.w - A.w);
            *(float4*)(s_v + p*64 + ci0b) = v;
        }
        __syncthreads();
        // GEMM: acc[i][j] += sum_ci wk[ci][co0+i] * v[p0+j][ci]
        #pragma unroll 4
        for (int cc = 0; cc < 64; cc += 4) {
            float4 va[4], wv[4];
            #pragma unroll
            for (int j = 0; j < 4; j++)
                va[j] = *(const float4*)(s_v + (p0+j)*64 + cc);
            #pragma unroll
            for (int c = 0; c < 4; c++)
                wv[c] = *(const float4*)(s_wk + (cc+c)*64 + co0);
            #pragma unroll
            for (int j = 0; j < 4; j++) {
                float4 vj = va[j];
                acc[0][j] += wv[0].x*vj.x + wv[1].x*vj.y + wv[2].x*vj.z + wv[3].x*vj.w;
                acc[1][j] += wv[0].y*vj.x + wv[1].y*vj.y + wv[2].y*vj.z + wv[3].y*vj.w;
                acc[2][j] += wv[0].z*vj.x + wv[1].z*vj.y + wv[2].z*vj.z + wv[3].z*vj.w;
                acc[3][j] += wv[0].w*vj.x + wv[1].w*vj.y + wv[2].w*vj.z + wv[3].w*vj.w;
            }
        }
    }

    // epilogue: bias, write raw, reduce GN2 partial stats
    float psum = 0.f, psq = 0.f;
    #pragma unroll
    for (int i = 0; i < 4; i++) {
        float bv = b_dsc[co0+i];
        float4 o4;
        float* op = (float*)&o4;
        #pragma unroll
        for (int j = 0; j < 4; j++) {
            float v = acc[i][j] + bv;
            op[j] = v;
            psum += v;
            psq  += v*v;
        }
        *(float4*)&g_outraw[((b*COUT + co0+i)*HH + h)*WW + w0 + p0] = o4;
    }
    s_red[t]       = psum;
    s_red[256 + t] = psq;
    __syncthreads();
    if (t < 16) {   // group g == t (co0/4 == t&15)
        float sm = 0.f, sq = 0.f;
        #pragma unroll
        for (int j = 0; j < 16; j++) {
            sm += s_red[t + 16*j];
            sq += s_red[256 + t + 16*j];
        }
        atomicAdd(&g_stats2[(b*16 + t)*2 + 0], sm);
        atomicAdd(&g_stats2[(b*16 + t)*2 + 1], sq);
    }
}

// ------------- finalize: GN2 + ReLU -------------
__global__ void finalize_kernel(const float* __restrict__ g_gn,
                                const float* __restrict__ b_gn,
                                float* __restrict__ out) {
    int idx = blockIdx.x*256 + threadIdx.x;   // 4*64*16384 = 4194304 exactly
    int b  = idx >> 20;
    int co = (idx >> 14) & 63;
    int g  = co >> 2;
    float s = g_stats2[(b*16+g)*2+0];
    float q = g_stats2[(b*16+g)*2+1];
    float mean = s * (1.f/65536.f);
    float var  = q * (1.f/65536.f) - mean*mean;
    float inv  = rsqrtf(var + 1e-5f);
    float v = (g_outraw[idx] - mean)*inv*g_gn[co] + b_gn[co];
    out[idx] = fmaxf(v, 0.f);
}

// ------------- launch -------------
extern "C" void kernel_launch(void* const* d_in, const int* in_sizes, int n_in,
                              void* d_out, int out_size) {
    const float* x        = (const float*)d_in[0];
    const float* w_off    = (const float*)d_in[1];
    const float* b_off    = (const float*)d_in[2];
    const float* g_gn_off = (const float*)d_in[3];
    const float* b_gn_off = (const float*)d_in[4];
    const float* w_dsc    = (const float*)d_in[5];
    const float* b_dsc    = (const float*)d_in[6];
    const float* g_gn     = (const float*)d_in[7];
    const float* b_gn     = (const float*)d_in[8];
    float* out = (float*)d_out;

    prep_kernel<<<144, 256>>>(w_dsc);
    conv1_kernel<<<dim3(1,32,4), dim3(32,4)>>>(x, w_off, b_off);
    transpose_kernel<<<dim3(512,2,4), dim3(32,8)>>>(x);
    fused_kernel<<<dim3(2,128,4), 256>>>(g_gn_off, b_gn_off, b_dsc);
    finalize_kernel<<<16384, 256>>>(g_gn, b_gn, out);
}